// round 10
// baseline (speedup 1.0000x reference)
#include <cuda_runtime.h>
#include <cuda_bf16.h>
#include <cuda_pipeline.h>
#include <cstdint>

// Problem constants
#define Nn   8
#define Cc   256
#define Hh   64
#define Ww   64
#define HWp  4096          // H*W
#define Gr   8             // groups
#define KK2  9             // K*K
#define GKK  72            // G*K*K
#define HIDc 256
#define HCc  16
#define NCHW (8*256*4096)
#define CSPLIT 4
#define CPB   (Cc/CSPLIT)            // 64 channels per block (2 filter groups)
#define NBLK_MAIN (2*Nn*8*CSPLIT)    // 512 : 8 tiles (4x in x, 2 in y)

// ---------------- packed f32x2 helpers (Blackwell) ----------------
__device__ __forceinline__ unsigned long long pack2(float v) {
    unsigned long long r;
    asm("mov.b64 %0, {%1, %1};" : "=l"(r) : "f"(v));
    return r;
}
__device__ __forceinline__ void fma2(unsigned long long& d,
                                     unsigned long long a, unsigned long long b) {
    asm("fma.rn.f32x2 %0, %1, %2, %0;" : "+l"(d) : "l"(a), "l"(b));
}
__device__ __forceinline__ float2 unpack2(unsigned long long v) {
    float2 r;
    asm("mov.b64 {%0, %1}, %2;" : "=f"(r.x), "=f"(r.y) : "l"(v));
    return r;
}

// ---------------- scratch (device globals: no allocation allowed) ----------------
__device__ float  g_gap[2][Nn][Cc];              // per-modality GAP
__device__ float  g_hid[2][Nn][HIDc];            // MLP hidden activations
__device__ float  g_filt[2][Nn][GKK];            // softmaxed dynamic filters
__device__ float2 g_wAB[2][Nn][Cc];              // (wR - wT, wT) gating per channel
__device__ float  g_Fp[2][CSPLIT][Nn][HCc][HWp]; // partial 16-ch features (no bias)
__device__ float  g_bsum[NBLK_MAIN][HCc];        // per-block partial sums for Gf mean

// ---------------- Kernel 1: GAP over H,W (+ copy R to output) ----------------
__global__ void k_gap(const float* __restrict__ R, const float* __restrict__ T,
                      float* __restrict__ outR)
{
    int b   = blockIdx.x;          // 0..4095 : mod*2048 + (n*256+c)
    int mod = b >> 11;
    int nc  = b & 2047;
    const float4* p = (const float4*)((mod ? T : R) + (size_t)nc * HWp);
    float4* q = (mod == 0 && outR) ? (float4*)(outR + (size_t)nc * HWp) : nullptr;
    int t = threadIdx.x;           // 128 threads
    float s = 0.f;
#pragma unroll
    for (int i = 0; i < 8; i++) {
        float4 v = p[t + 128 * i];
        if (q) q[t + 128 * i] = v;
        s += v.x + v.y + v.z + v.w;
    }
#pragma unroll
    for (int o = 16; o; o >>= 1) s += __shfl_down_sync(0xffffffffu, s, o);
    __shared__ float sm[4];
    if ((t & 31) == 0) sm[t >> 5] = s;
    __syncthreads();
    if (t == 0)
        g_gap[mod][nc >> 8][nc & 255] = (sm[0] + sm[1] + sm[2] + sm[3]) * (1.f / 4096.f);
}

// ---------------- Kernel 2a: hidden layer + dynamic filters ----------------
__global__ void k_vecA(const float* __restrict__ conv_w,
                       const float* __restrict__ bn_g, const float* __restrict__ bn_b,
                       const float* __restrict__ bn_m, const float* __restrict__ bn_v,
                       const float* __restrict__ f1W1, const float* __restrict__ f1b1,
                       const float* __restrict__ f2W1, const float* __restrict__ f2b1)
{
    int b = blockIdx.x;
    int j = b % 9;
    int n = (b / 9) & 7;
    int mod = b / 72;
    const float* W1 = mod ? f2W1 : f1W1;
    const float* b1 = mod ? f2b1 : f1b1;

    __shared__ float gp[Cc];
    __shared__ float part[8][32];
    __shared__ float lf_sm[GKK];
    int t = threadIdx.x;          // 256
    gp[t] = g_gap[mod][n][t];
    __syncthreads();

    int lane = t & 31, w = t >> 5;
    if (j < 8) {
        int o = j * 32 + lane;
        const float* Wp = W1 + (size_t)(w * 32) * HIDc + o;
        float s = 0.f;
#pragma unroll
        for (int i = 0; i < 32; i++) s += gp[w * 32 + i] * Wp[(size_t)i * HIDc];
        part[w][lane] = s;
        __syncthreads();
        if (t < 32) {
            float a = b1[j * 32 + t];
#pragma unroll
            for (int ww = 0; ww < 8; ww++) a += part[ww][t];
            g_hid[mod][n][j * 32 + t] = fmaxf(a, 0.f);
        }
    } else {
#pragma unroll
        for (int k = 0; k < KK2; k++) {
            int o = w * KK2 + k;
            const float* cw = conv_w + (size_t)o * Cc;
            float a = 0.f;
#pragma unroll
            for (int q = 0; q < 8; q++) a += gp[lane + 32 * q] * cw[lane + 32 * q];
#pragma unroll
            for (int off = 16; off; off >>= 1) a += __shfl_down_sync(0xffffffffu, a, off);
            if (lane == 0)
                lf_sm[o] = (a - bn_m[o]) * rsqrtf(bn_v[o] + 1e-5f) * bn_g[o] + bn_b[o];
        }
        __syncthreads();
        if (t < Gr) {
            float mx = -1e30f;
#pragma unroll
            for (int k = 0; k < KK2; k++) mx = fmaxf(mx, lf_sm[t * KK2 + k]);
            float e[KK2], sum = 0.f;
#pragma unroll
            for (int k = 0; k < KK2; k++) { e[k] = expf(lf_sm[t * KK2 + k] - mx); sum += e[k]; }
            float inv = 1.f / sum;
#pragma unroll
            for (int k = 0; k < KK2; k++) g_filt[mod][n][t * KK2 + k] = e[k] * inv;
        }
    }
}

// ---------------- Kernel 2b: sigmoid gating layers ----------------
__global__ void k_vecB(const float* __restrict__ f1W2R, const float* __restrict__ f1b2R,
                       const float* __restrict__ f1W2T, const float* __restrict__ f1b2T,
                       const float* __restrict__ f2W2R, const float* __restrict__ f2b2R,
                       const float* __restrict__ f2W2T, const float* __restrict__ f2b2T)
{
    int b = blockIdx.x;
    int half = b & 1;
    int n = (b >> 1) & 7;
    int mod = b >> 4;
    const float* W2R = mod ? f2W2R : f1W2R;
    const float* b2R = mod ? f2b2R : f1b2R;
    const float* W2T = mod ? f2W2T : f1W2T;
    const float* b2T = mod ? f2b2T : f1b2T;

    __shared__ float hid_sm[HIDc];
    __shared__ float psR[8][128], psT[8][128];
    int t = threadIdx.x;          // 256
    hid_sm[t] = g_hid[mod][n][t];
    __syncthreads();

    int lane = t & 31, w = t >> 5;
#pragma unroll
    for (int ch = 0; ch < 4; ch++) {
        int o = half * 128 + ch * 32 + lane;
        float aR = 0.f, aT = 0.f;
#pragma unroll
        for (int i2 = 0; i2 < 32; i2++) {
            float h = hid_sm[w * 32 + i2];
            size_t idx = (size_t)(w * 32 + i2) * Cc + o;
            aR += h * W2R[idx];
            aT += h * W2T[idx];
        }
        psR[w][ch * 32 + lane] = aR;
        psT[w][ch * 32 + lane] = aT;
    }
    __syncthreads();
    if (t < 128) {
        int o = half * 128 + t;
        float aR = b2R[o], aT = b2T[o];
#pragma unroll
        for (int ww = 0; ww < 8; ww++) { aR += psR[ww][t]; aT += psT[ww][t]; }
        float wR = 1.f / (1.f + expf(-aR));
        float wT = 1.f / (1.f + expf(-aT));
        g_wAB[mod][n][o] = make_float2(wR - wT, wT);
    }
}

// ---------------- Kernel 3: involution + gating + 256->16 conv ----------------
// grid = 512: (((mod*8 + n)*8 + tile)*4 + cs), tile = tyt*4+txt (16x32 tiles),
// 64 channels (2 filter groups) per block, 256 threads, 2 vertical px/thread.
// cp.async pipeline: 8 channel buffers, single barrier/channel, f32x2 conv-16.
#define HSTR  24
#define ROWS  34
#define BUFSZ (ROWS * HSTR)
__global__ void __launch_bounds__(256, 3) k_main(const float* __restrict__ R,
                                                 const float* __restrict__ T,
                                                 const float* __restrict__ fv_wR,
                                                 const float* __restrict__ fv_wT)
{
    int b    = blockIdx.x;
    int cs   = b & 3;
    int r    = b >> 2;
    int tile = r & 7;
    r >>= 3;
    int n    = r & 7;
    int mod  = r >> 3;
    int tx0  = (tile & 3) * 16;
    int ty0  = (tile >> 2) * 32;

    const float* X    = (mod ? T : R) + (size_t)n * Cc * HWp + (size_t)cs * CPB * HWp;
    const float* wmat = mod ? fv_wT : fv_wR;      // [16][256]
    float* Out = &g_Fp[mod][cs][n][0][0];

    __shared__ float  buf[8][BUFSZ];
    __shared__ float  wv[CPB * HCc];       // transposed: wv[c*16+o], c local
    __shared__ float2 ab_sm[CPB];
    __shared__ float  filt_sm[2 * KK2];
    __shared__ float  red[8][HCc];

    int t = threadIdx.x;
    for (int i = t; i < CPB * HCc; i += 256) {
        int o = i >> 6, c = i & 63;
        wv[c * HCc + o] = wmat[o * Cc + cs * CPB + c];
    }
    if (t < CPB) ab_sm[t] = g_wAB[mod][n][cs * CPB + t];
    if (t < 2 * KK2) filt_sm[t] = g_filt[mod][n][cs * 2 * KK2 + t];

    // ---- cp.async op tables ----
    // 16B ops: 34 rows x 4 chunks = 136 (t<136); 4B halo: 34 x 2 = 68 (t<68)
    auto refl = [](int gy) { return gy < 0 ? 1 : (gy > 63 ? 62 : gy); };
    bool has16 = t < 136;
    int i16 = has16 ? t : 0;
    int ra = i16 >> 2, sa = i16 & 3;
    int g16 = refl(ty0 - 1 + ra) * Ww + tx0 + sa * 4;
    int s16 = ra * HSTR + sa * 4;
    bool has4 = t < 68;
    int j4 = has4 ? t : 0;
    int rc = j4 >> 1, side = j4 & 1;
    int gx4 = side ? (tx0 + 16 > 63 ? 62 : tx0 + 16) : (tx0 == 0 ? 1 : tx0 - 1);
    int g4 = refl(ty0 - 1 + rc) * Ww + gx4;
    int s4 = rc * HSTR + 16 + side;

    int tx = t & 15, ty = t >> 4;
    int y0l = ty * 2;              // local output rows y0l, y0l+1 (0..31)
    int wb0 = y0l * HSTR;          // smem row of (global y0l-1 rel. to halo)
    int offL = (tx == 0)  ? 16 : tx - 1;
    int off0 = tx;
    int offR = (tx == 15) ? 17 : tx + 1;

    unsigned long long accp[2][8];  // f32x2: lanes (hc=2q, hc=2q+1)
#pragma unroll
    for (int j = 0; j < 2; j++)
#pragma unroll
        for (int q = 0; q < 8; q++) accp[j][q] = 0ull;

    __syncthreads();               // wv/ab/filt visible
    float f[KK2];
#pragma unroll
    for (int k = 0; k < KK2; k++) f[k] = filt_sm[k];

    // pipeline prologue: channels 0,1,2
#pragma unroll
    for (int p = 0; p < 3; p++) {
        const float* S = X + (size_t)p * HWp;
        float* D = buf[p];
        if (has16) __pipeline_memcpy_async(&D[s16], &S[g16], 16);
        if (has4)  __pipeline_memcpy_async(&D[s4],  &S[g4],  4);
        __pipeline_commit();
    }

    for (int c = 0; c < CPB; c++) {
        {   // issue channel c+3 (ring distance 4 from slowest reader)
            int q = c + 3;
            if (q < CPB) {
                const float* S = X + (size_t)q * HWp;
                float* D = buf[q & 7];
                if (has16) __pipeline_memcpy_async(&D[s16], &S[g16], 16);
                if (has4)  __pipeline_memcpy_async(&D[s4],  &S[g4],  4);
            }
            __pipeline_commit();
        }
        __pipeline_wait_prior(3);
        __syncthreads();           // single barrier per channel

        if (c == 32) {             // second filter group
#pragma unroll
            for (int k = 0; k < KK2; k++) f[k] = filt_sm[KK2 + k];
        }
        const float* Bf = &buf[c & 7][wb0];
        float2 ab = ab_sm[c];
        float lo0, lo1, ctr0, ctr1;
        {
            float wa = Bf[offL],            wbv = Bf[off0],            wc = Bf[offR];
            lo0 = f[0]*wa + f[1]*wbv + f[2]*wc;
        }
        {
            float wa = Bf[HSTR+offL],       wbv = Bf[HSTR+off0],       wc = Bf[HSTR+offR];
            lo0 += f[3]*wa + f[4]*wbv + f[5]*wc;
            lo1  = f[0]*wa + f[1]*wbv + f[2]*wc;
            ctr0 = wbv;
        }
        {
            float wa = Bf[2*HSTR+offL],     wbv = Bf[2*HSTR+off0],     wc = Bf[2*HSTR+offR];
            lo0 += f[6]*wa + f[7]*wbv + f[8]*wc;
            lo1 += f[3]*wa + f[4]*wbv + f[5]*wc;
            ctr1 = wbv;
        }
        {
            float wa = Bf[3*HSTR+offL],     wbv = Bf[3*HSTR+off0],     wc = Bf[3*HSTR+offR];
            lo1 += f[6]*wa + f[7]*wbv + f[8]*wc;
        }
        unsigned long long v0 = pack2(ab.y * ctr0 + ab.x * lo0);
        unsigned long long v1 = pack2(ab.y * ctr1 + ab.x * lo1);
        const unsigned long long* wp = (const unsigned long long*)&wv[c * HCc];
#pragma unroll
        for (int q = 0; q < 8; q++) {
            unsigned long long w2 = wp[q];
            fma2(accp[0][q], w2, v0);
            fma2(accp[1][q], w2, v1);
        }
    }

    // store partial outputs (no bias)
    int x = tx0 + tx, yg = ty0 + y0l;
#pragma unroll
    for (int q = 0; q < 8; q++) {
        float2 u0 = unpack2(accp[0][q]);
        float2 u1 = unpack2(accp[1][q]);
        Out[(2*q)   * HWp + yg * Ww + x]       = u0.x;
        Out[(2*q+1) * HWp + yg * Ww + x]       = u0.y;
        Out[(2*q)   * HWp + (yg+1) * Ww + x]   = u1.x;
        Out[(2*q+1) * HWp + (yg+1) * Ww + x]   = u1.y;
    }

    // deterministic per-block reduction for the Gf-mean path
    int lane = t & 31, w = t >> 5;
#pragma unroll
    for (int q = 0; q < 8; q++) {
        float2 s0 = unpack2(accp[0][q]), s1 = unpack2(accp[1][q]);
        float vx = s0.x + s1.x;
        float vy = s0.y + s1.y;
#pragma unroll
        for (int o = 16; o; o >>= 1) {
            vx += __shfl_down_sync(0xffffffffu, vx, o);
            vy += __shfl_down_sync(0xffffffffu, vy, o);
        }
        if (lane == 0) { red[w][2*q] = vx; red[w][2*q+1] = vy; }
    }
    __syncthreads();
    if (t < HCc) {
        float s = 0.f;
#pragma unroll
        for (int ww = 0; ww < 8; ww++) s += red[ww][t];
        g_bsum[blockIdx.x][t] = s;
    }
}

// ---------------- Kernel 4: fovea softmax + wG gate + 16->256 conv ----------------
__global__ void __launch_bounds__(256) k_out(const float* __restrict__ wO,
                                             const float* __restrict__ bO,
                                             const float* __restrict__ sRp,
                                             const float* __restrict__ sTp,
                                             const float* __restrict__ bR,
                                             const float* __restrict__ bT,
                                             const float* __restrict__ Lw,
                                             const float* __restrict__ Lb,
                                             float* __restrict__ out)
{
    int b = blockIdx.x;            // 512: n*64 + y
    int n = b >> 6, y = b & 63;
    __shared__ float  sR[HCc * Ww], sT[HCc * Ww], fu[HCc * Ww];
    __shared__ float4 wo[Cc * 4];  // wO rows as float4: wo[co*4+q]
    __shared__ float  bo[Cc];
    __shared__ float  red2[8][HCc], meansm[HCc], wg_sm[HCc];
    int t = threadIdx.x;

    // inline wG: sum g_bsum over this n's 64 k_main blocks
    if (t < 128) {
        int hc = t & 15, sl = t >> 4;   // 8 slices x 8 rows
        float s = 0.f;
#pragma unroll
        for (int k = 0; k < 8; k++) {
            int rr = sl * 8 + k;        // 0..63 : mod*32 + tile*4 + cs
            int mod = rr >> 5, rem = rr & 31;
            int idx = (((mod * 8 + n) * 8) + (rem >> 2)) * 4 + (rem & 3);
            s += g_bsum[idx][hc];
        }
        red2[sl][hc] = s;
    }

#pragma unroll
    for (int i = t; i < HCc * Ww; i += 256) {
        int hc = i >> 6, x = i & 63;
        int off = hc * HWp + y * Ww + x;
        float r = bR[hc], tv = bT[hc];
#pragma unroll
        for (int cs = 0; cs < CSPLIT; cs++) {
            r  += g_Fp[0][cs][n][0][off];
            tv += g_Fp[1][cs][n][0][off];
        }
        sR[i] = r;
        sT[i] = tv;
    }
    for (int i = t; i < Cc * 4; i += 256) wo[i] = ((const float4*)wO)[i];
    bo[t] = bO[t];
    float scR = sRp[0], scT = sTp[0];
    __syncthreads();

    if (t < HCc) {
        float a = 0.f;
#pragma unroll
        for (int k = 0; k < 8; k++) a += red2[k][t];
        meansm[t] = a * (1.f / 4096.f) + bR[t] + bT[t];
    }
    __syncthreads();
    if (t < HCc) {
        float a = Lb[t];
#pragma unroll
        for (int i = 0; i < HCc; i++) a += meansm[i] * Lw[i * HCc + t];
        wg_sm[t] = 1.f / (1.f + expf(-a));
    }
    __syncthreads();

    int lane = t & 31, w = t >> 5;
#pragma unroll
    for (int hh = 0; hh < 2; hh++) {
        int hc = w + hh * 8;
        float rf0 = sR[hc * Ww + lane], rf1 = sR[hc * Ww + lane + 32];
        float tf0 = sT[hc * Ww + lane], tf1 = sT[hc * Ww + lane + 32];
        float a0 = rf0 * scR, a1 = rf1 * scR;
        float m = fmaxf(a0, a1);
#pragma unroll
        for (int o = 16; o; o >>= 1) m = fmaxf(m, __shfl_xor_sync(0xffffffffu, m, o));
        float e0 = expf(a0 - m), e1 = expf(a1 - m);
        float s = e0 + e1;
#pragma unroll
        for (int o = 16; o; o >>= 1) s += __shfl_xor_sync(0xffffffffu, s, o);
        float inv = 1.f / s;
        float mR0 = e0 * inv, mR1 = e1 * inv;
        float c0 = tf0 * scT, c1 = tf1 * scT;
        float mt = fmaxf(c0, c1);
#pragma unroll
        for (int o = 16; o; o >>= 1) mt = fmaxf(mt, __shfl_xor_sync(0xffffffffu, mt, o));
        float g0 = expf(c0 - mt), g1 = expf(c1 - mt);
        float st = g0 + g1;
#pragma unroll
        for (int o = 16; o; o >>= 1) st += __shfl_xor_sync(0xffffffffu, st, o);
        float invt = 1.f / st;
        float mT0 = g0 * invt, mT1 = g1 * invt;

        float wg = wg_sm[hc];
        fu[hc * Ww + lane]      = mR0 * rf0 + mT0 * tf0 + wg * (rf0 + tf0);
        fu[hc * Ww + lane + 32] = mR1 * rf1 + mT1 * tf1 + wg * (rf1 + tf1);
    }
    __syncthreads();

    int x = t & 63, co0 = t >> 6;
    float fx[HCc];
#pragma unroll
    for (int i = 0; i < HCc; i++) fx[i] = fu[i * Ww + x];
    float* outp = out + (size_t)n * Cc * HWp + y * Ww + x;
    for (int co = co0; co < Cc; co += 4) {
        const float4* wp = &wo[co * 4];
        float a = bo[co];
#pragma unroll
        for (int q = 0; q < 4; q++) {
            float4 ww = wp[q];
            a += ww.x * fx[q*4+0] + ww.y * fx[q*4+1] + ww.z * fx[q*4+2] + ww.w * fx[q*4+3];
        }
        outp[(size_t)co * HWp] = a;
    }
}

// ---------------- launch ----------------
extern "C" void kernel_launch(void* const* d_in, const int* in_sizes, int n_in,
                              void* d_out, int out_size)
{
    const float* R      = (const float*)d_in[0];
    const float* T      = (const float*)d_in[1];
    const float* conv_w = (const float*)d_in[2];
    const float* bn_g   = (const float*)d_in[3];
    const float* bn_b   = (const float*)d_in[4];
    const float* bn_m   = (const float*)d_in[5];
    const float* bn_v   = (const float*)d_in[6];
    const float* f1W1   = (const float*)d_in[7];
    const float* f1b1   = (const float*)d_in[8];
    const float* f1W2R  = (const float*)d_in[9];
    const float* f1b2R  = (const float*)d_in[10];
    const float* f1W2T  = (const float*)d_in[11];
    const float* f1b2T  = (const float*)d_in[12];
    const float* f2W1   = (const float*)d_in[13];
    const float* f2b1   = (const float*)d_in[14];
    const float* f2W2R  = (const float*)d_in[15];
    const float* f2b2R  = (const float*)d_in[16];
    const float* f2W2T  = (const float*)d_in[17];
    const float* f2b2T  = (const float*)d_in[18];
    const float* fv_wR  = (const float*)d_in[19];
    const float* fv_bR  = (const float*)d_in[20];
    const float* fv_wT  = (const float*)d_in[21];
    const float* fv_bT  = (const float*)d_in[22];
    const float* fv_Lw  = (const float*)d_in[23];
    const float* fv_Lb  = (const float*)d_in[24];
    const float* fv_wO  = (const float*)d_in[25];
    const float* fv_bO  = (const float*)d_in[26];
    const float* fv_sR  = (const float*)d_in[27];
    const float* fv_sT  = (const float*)d_in[28];

    float* out  = (float*)d_out;
    float* outR = nullptr;
    float* outO = out;
    if (out_size >= 2 * NCHW) {   // output is (R, out) concatenated
        outR = out;
        outO = out + NCHW;
    }

    k_gap<<<4096, 128>>>(R, T, outR);
    k_vecA<<<144, 256>>>(conv_w, bn_g, bn_b, bn_m, bn_v,
                         f1W1, f1b1, f2W1, f2b1);
    k_vecB<<<32, 256>>>(f1W2R, f1b2R, f1W2T, f1b2T,
                        f2W2R, f2b2R, f2W2T, f2b2T);
    k_main<<<NBLK_MAIN, 256>>>(R, T, fv_wR, fv_wT);
    k_out<<<512, 256>>>(fv_wO, fv_bO, fv_sR, fv_sT, fv_bR, fv_bT,
                        fv_Lw, fv_Lb, outO);
}

// round 11
// speedup vs baseline: 1.0822x; 1.0822x over previous
#include <cuda_runtime.h>
#include <cuda_bf16.h>
#include <cuda_pipeline.h>
#include <cstdint>

// Problem constants
#define Nn   8
#define Cc   256
#define Hh   64
#define Ww   64
#define HWp  4096          // H*W
#define Gr   8             // groups
#define KK2  9             // K*K
#define GKK  72            // G*K*K
#define HIDc 256
#define HCc  16
#define NCHW (8*256*4096)
#define CSPLIT 8
#define CPB   (Cc/CSPLIT)            // 32 channels per block (= one filter group)
#define XT    4                      // x tiles of width 16 (full height)
#define NBLK_MAIN (2*Nn*XT*CSPLIT)   // 512

// ---------------- packed f32x2 helpers (Blackwell) ----------------
__device__ __forceinline__ unsigned long long pack2(float v) {
    unsigned long long r;
    asm("mov.b64 %0, {%1, %1};" : "=l"(r) : "f"(v));
    return r;
}
__device__ __forceinline__ void fma2(unsigned long long& d,
                                     unsigned long long a, unsigned long long b) {
    asm("fma.rn.f32x2 %0, %1, %2, %0;" : "+l"(d) : "l"(a), "l"(b));
}
__device__ __forceinline__ float2 unpack2(unsigned long long v) {
    float2 r;
    asm("mov.b64 {%0, %1}, %2;" : "=f"(r.x), "=f"(r.y) : "l"(v));
    return r;
}

// ---------------- scratch (device globals: no allocation allowed) ----------------
__device__ float  g_gap[2][Nn][Cc];              // per-modality GAP
__device__ float  g_hid[2][Nn][HIDc];            // MLP hidden activations
__device__ float  g_filt[2][Nn][GKK];            // softmaxed dynamic filters
__device__ float2 g_wAB[2][Nn][Cc];              // (wR - wT, wT) gating per channel
__device__ float  g_Fp[2][CSPLIT][Nn][HCc][HWp]; // partial 16-ch features (no bias)
__device__ float  g_bsum[NBLK_MAIN][HCc];        // per-block partial sums for Gf mean

// ---------------- Kernel 1: GAP over H,W (+ copy R to output) ----------------
__global__ void k_gap(const float* __restrict__ R, const float* __restrict__ T,
                      float* __restrict__ outR)
{
    int b   = blockIdx.x;          // 0..4095 : mod*2048 + (n*256+c)
    int mod = b >> 11;
    int nc  = b & 2047;
    const float4* p = (const float4*)((mod ? T : R) + (size_t)nc * HWp);
    float4* q = (mod == 0 && outR) ? (float4*)(outR + (size_t)nc * HWp) : nullptr;
    int t = threadIdx.x;           // 128 threads
    float s = 0.f;
#pragma unroll
    for (int i = 0; i < 8; i++) {
        float4 v = p[t + 128 * i];
        if (q) q[t + 128 * i] = v;
        s += v.x + v.y + v.z + v.w;
    }
#pragma unroll
    for (int o = 16; o; o >>= 1) s += __shfl_down_sync(0xffffffffu, s, o);
    __shared__ float sm[4];
    if ((t & 31) == 0) sm[t >> 5] = s;
    __syncthreads();
    if (t == 0)
        g_gap[mod][nc >> 8][nc & 255] = (sm[0] + sm[1] + sm[2] + sm[3]) * (1.f / 4096.f);
}

// ---------------- Kernel 2a: hidden layer + dynamic filters ----------------
__global__ void k_vecA(const float* __restrict__ conv_w,
                       const float* __restrict__ bn_g, const float* __restrict__ bn_b,
                       const float* __restrict__ bn_m, const float* __restrict__ bn_v,
                       const float* __restrict__ f1W1, const float* __restrict__ f1b1,
                       const float* __restrict__ f2W1, const float* __restrict__ f2b1)
{
    int b = blockIdx.x;
    int j = b % 9;
    int n = (b / 9) & 7;
    int mod = b / 72;
    const float* W1 = mod ? f2W1 : f1W1;
    const float* b1 = mod ? f2b1 : f1b1;

    __shared__ float gp[Cc];
    __shared__ float part[8][32];
    __shared__ float lf_sm[GKK];
    int t = threadIdx.x;          // 256
    gp[t] = g_gap[mod][n][t];
    __syncthreads();

    int lane = t & 31, w = t >> 5;
    if (j < 8) {
        int o = j * 32 + lane;
        const float* Wp = W1 + (size_t)(w * 32) * HIDc + o;
        float s = 0.f;
#pragma unroll
        for (int i = 0; i < 32; i++) s += gp[w * 32 + i] * Wp[(size_t)i * HIDc];
        part[w][lane] = s;
        __syncthreads();
        if (t < 32) {
            float a = b1[j * 32 + t];
#pragma unroll
            for (int ww = 0; ww < 8; ww++) a += part[ww][t];
            g_hid[mod][n][j * 32 + t] = fmaxf(a, 0.f);
        }
    } else {
#pragma unroll
        for (int k = 0; k < KK2; k++) {
            int o = w * KK2 + k;
            const float* cw = conv_w + (size_t)o * Cc;
            float a = 0.f;
#pragma unroll
            for (int q = 0; q < 8; q++) a += gp[lane + 32 * q] * cw[lane + 32 * q];
#pragma unroll
            for (int off = 16; off; off >>= 1) a += __shfl_down_sync(0xffffffffu, a, off);
            if (lane == 0)
                lf_sm[o] = (a - bn_m[o]) * rsqrtf(bn_v[o] + 1e-5f) * bn_g[o] + bn_b[o];
        }
        __syncthreads();
        if (t < Gr) {
            float mx = -1e30f;
#pragma unroll
            for (int k = 0; k < KK2; k++) mx = fmaxf(mx, lf_sm[t * KK2 + k]);
            float e[KK2], sum = 0.f;
#pragma unroll
            for (int k = 0; k < KK2; k++) { e[k] = expf(lf_sm[t * KK2 + k] - mx); sum += e[k]; }
            float inv = 1.f / sum;
#pragma unroll
            for (int k = 0; k < KK2; k++) g_filt[mod][n][t * KK2 + k] = e[k] * inv;
        }
    }
}

// ---------------- Kernel 2b: sigmoid gating layers ----------------
__global__ void k_vecB(const float* __restrict__ f1W2R, const float* __restrict__ f1b2R,
                       const float* __restrict__ f1W2T, const float* __restrict__ f1b2T,
                       const float* __restrict__ f2W2R, const float* __restrict__ f2b2R,
                       const float* __restrict__ f2W2T, const float* __restrict__ f2b2T)
{
    int b = blockIdx.x;
    int half = b & 1;
    int n = (b >> 1) & 7;
    int mod = b >> 4;
    const float* W2R = mod ? f2W2R : f1W2R;
    const float* b2R = mod ? f2b2R : f1b2R;
    const float* W2T = mod ? f2W2T : f1W2T;
    const float* b2T = mod ? f2b2T : f1b2T;

    __shared__ float hid_sm[HIDc];
    __shared__ float psR[8][128], psT[8][128];
    int t = threadIdx.x;          // 256
    hid_sm[t] = g_hid[mod][n][t];
    __syncthreads();

    int lane = t & 31, w = t >> 5;
#pragma unroll
    for (int ch = 0; ch < 4; ch++) {
        int o = half * 128 + ch * 32 + lane;
        float aR = 0.f, aT = 0.f;
#pragma unroll
        for (int i2 = 0; i2 < 32; i2++) {
            float h = hid_sm[w * 32 + i2];
            size_t idx = (size_t)(w * 32 + i2) * Cc + o;
            aR += h * W2R[idx];
            aT += h * W2T[idx];
        }
        psR[w][ch * 32 + lane] = aR;
        psT[w][ch * 32 + lane] = aT;
    }
    __syncthreads();
    if (t < 128) {
        int o = half * 128 + t;
        float aR = b2R[o], aT = b2T[o];
#pragma unroll
        for (int ww = 0; ww < 8; ww++) { aR += psR[ww][t]; aT += psT[ww][t]; }
        float wR = 1.f / (1.f + expf(-aR));
        float wT = 1.f / (1.f + expf(-aT));
        g_wAB[mod][n][o] = make_float2(wR - wT, wT);
    }
}

// ---------------- Kernel 3: involution + gating + 256->16 conv ----------------
// grid = 512: ((mod*8 + n)*4 + tile)*8 + cs. Tile = 16 wide x 64 tall stripe,
// 32 channels (one filter group) per block. 256 threads, 4 vertical px/thread.
// cp.async pipeline: 8 channel buffers, depth-6 lookahead, single barrier/channel,
// 16B interior rows + 4B halo columns. Conv-16 in packed f32x2.
#define HSTR  20
#define ROWS  66
#define BUFSZ (ROWS * HSTR)
#define LOOKAHEAD 5
__global__ void __launch_bounds__(256, 2) k_main(const float* __restrict__ R,
                                                 const float* __restrict__ T,
                                                 const float* __restrict__ fv_wR,
                                                 const float* __restrict__ fv_wT)
{
    int b    = blockIdx.x;
    int cs   = b & 7;
    int r    = b >> 3;
    int tile = r & 3;
    r >>= 2;
    int n    = r & 7;
    int mod  = r >> 3;
    int tx0  = tile * 16;

    const float* X    = (mod ? T : R) + (size_t)n * Cc * HWp + (size_t)cs * CPB * HWp;
    const float* wmat = mod ? fv_wT : fv_wR;      // [16][256]
    float* Out = &g_Fp[mod][cs][n][0][0];

    __shared__ float  buf[8][BUFSZ];
    __shared__ float  wv[CPB * HCc];       // transposed: wv[c*16+o], c local
    __shared__ float2 ab_sm[CPB];
    __shared__ float  filt_sm[KK2];
    __shared__ float  red[8][HCc];

    int t = threadIdx.x;
    for (int i = t; i < CPB * HCc; i += 256) {
        int o = i >> 5, c = i & 31;
        wv[c * HCc + o] = wmat[o * Cc + cs * CPB + c];
    }
    if (t < CPB) ab_sm[t] = g_wAB[mod][n][cs * CPB + t];
    if (t < KK2) filt_sm[t] = g_filt[mod][n][cs * KK2 + t];   // group == cs

    // ---- cp.async op tables ----
    auto refl = [](int gy) { return gy < 0 ? 1 : (gy > 63 ? 62 : gy); };
    int i16a = t;
    int ra = i16a >> 2, sa = i16a & 3;
    int g16a = refl(ra - 1) * Ww + tx0 + sa * 4;
    int s16a = ra * HSTR + sa * 4;
    bool has16b = t < 8;
    int i16b = t + 256;
    int rb = i16b >> 2, sb = i16b & 3;
    int g16b = refl(rb - 1) * Ww + tx0 + sb * 4;
    int s16b = rb * HSTR + sb * 4;
    bool has4 = t < 132;
    int j4 = has4 ? t : 0;
    int rc = j4 >> 1, side = j4 & 1;
    int gx4 = side ? (tx0 + 16 > 63 ? 62 : tx0 + 16) : (tx0 == 0 ? 1 : tx0 - 1);
    int g4 = refl(rc - 1) * Ww + gx4;
    int s4 = rc * HSTR + 16 + side;

    int tx = t & 15, ty = t >> 4;
    int y0 = ty * 4;               // 4 output rows y0..y0+3
    int offL = (tx == 0)  ? 16 : tx - 1;
    int off0 = tx;
    int offR = (tx == 15) ? 17 : tx + 1;

    unsigned long long accp[4][8];  // f32x2: lanes (hc=2q, hc=2q+1)
#pragma unroll
    for (int j = 0; j < 4; j++)
#pragma unroll
        for (int q = 0; q < 8; q++) accp[j][q] = 0ull;

    __syncthreads();               // wv/ab/filt visible
    float f[KK2];
#pragma unroll
    for (int k = 0; k < KK2; k++) f[k] = filt_sm[k];

    // pipeline prologue: channels 0..LOOKAHEAD-1
#pragma unroll
    for (int p = 0; p < LOOKAHEAD; p++) {
        const float* S = X + (size_t)p * HWp;
        float* D = buf[p];
        __pipeline_memcpy_async(&D[s16a], &S[g16a], 16);
        if (has16b) __pipeline_memcpy_async(&D[s16b], &S[g16b], 16);
        if (has4)   __pipeline_memcpy_async(&D[s4],   &S[g4],   4);
        __pipeline_commit();
    }

    for (int c = 0; c < CPB; c++) {
        {   // issue channel c+LOOKAHEAD (ring distance 6 from slowest reader)
            int q = c + LOOKAHEAD;
            if (q < CPB) {
                const float* S = X + (size_t)q * HWp;
                float* D = buf[q & 7];
                __pipeline_memcpy_async(&D[s16a], &S[g16a], 16);
                if (has16b) __pipeline_memcpy_async(&D[s16b], &S[g16b], 16);
                if (has4)   __pipeline_memcpy_async(&D[s4],   &S[g4],   4);
            }
            __pipeline_commit();
        }
        __pipeline_wait_prior(LOOKAHEAD);
        __syncthreads();           // single barrier per channel

        const float* Bf = buf[c & 7];
        float2 ab = ab_sm[c];
        float Av[6], Bv[6], Cv[6];
#pragma unroll
        for (int rr = 0; rr < 6; rr++) {
            int o = (y0 + rr) * HSTR;
            Av[rr] = Bf[o + offL];
            Bv[rr] = Bf[o + off0];
            Cv[rr] = Bf[o + offR];
        }
        const unsigned long long* wp = (const unsigned long long*)&wv[c * HCc];
        unsigned long long w2[8];
#pragma unroll
        for (int q = 0; q < 8; q++) w2[q] = wp[q];
#pragma unroll
        for (int j = 0; j < 4; j++) {
            float low = f[0]*Av[j]   + f[1]*Bv[j]   + f[2]*Cv[j]
                      + f[3]*Av[j+1] + f[4]*Bv[j+1] + f[5]*Cv[j+1]
                      + f[6]*Av[j+2] + f[7]*Bv[j+2] + f[8]*Cv[j+2];
            float val = ab.y * Bv[j+1] + ab.x * low;   // wT*X + (wR-wT)*low
            unsigned long long v2 = pack2(val);
#pragma unroll
            for (int q = 0; q < 8; q++) fma2(accp[j][q], w2[q], v2);
        }
    }

    // store partial outputs (no bias)
    int x = tx0 + tx;
#pragma unroll
    for (int q = 0; q < 8; q++)
#pragma unroll
        for (int j = 0; j < 4; j++) {
            float2 u = unpack2(accp[j][q]);
            Out[(2 * q)     * HWp + (y0 + j) * Ww + x] = u.x;
            Out[(2 * q + 1) * HWp + (y0 + j) * Ww + x] = u.y;
        }

    // deterministic per-block reduction for the Gf-mean path
    int lane = t & 31, w = t >> 5;
#pragma unroll
    for (int q = 0; q < 8; q++) {
        float2 s0 = unpack2(accp[0][q]), s1 = unpack2(accp[1][q]);
        float2 s2 = unpack2(accp[2][q]), s3 = unpack2(accp[3][q]);
        float vx = s0.x + s1.x + s2.x + s3.x;
        float vy = s0.y + s1.y + s2.y + s3.y;
#pragma unroll
        for (int o = 16; o; o >>= 1) {
            vx += __shfl_down_sync(0xffffffffu, vx, o);
            vy += __shfl_down_sync(0xffffffffu, vy, o);
        }
        if (lane == 0) { red[w][2 * q] = vx; red[w][2 * q + 1] = vy; }
    }
    __syncthreads();
    if (t < HCc) {
        float s = 0.f;
#pragma unroll
        for (int ww = 0; ww < 8; ww++) s += red[ww][t];
        g_bsum[blockIdx.x][t] = s;
    }
}

// ---------------- Kernel 4: fovea softmax + inline wG gate + 16->256 conv ----------
__global__ void __launch_bounds__(256) k_out(const float* __restrict__ wO,
                                             const float* __restrict__ bO,
                                             const float* __restrict__ sRp,
                                             const float* __restrict__ sTp,
                                             const float* __restrict__ bR,
                                             const float* __restrict__ bT,
                                             const float* __restrict__ Lw,
                                             const float* __restrict__ Lb,
                                             float* __restrict__ out)
{
    int b = blockIdx.x;            // 512: n*64 + y
    int n = b >> 6, y = b & 63;
    __shared__ float  sR[HCc * Ww], sT[HCc * Ww], fu[HCc * Ww];
    __shared__ float4 wo[Cc * 4];  // wO rows as float4: wo[co*4+q]
    __shared__ float  bo[Cc];
    __shared__ float  red2[8][HCc], meansm[HCc], wg_sm[HCc];
    int t = threadIdx.x;

    // inline wG: sum g_bsum over this n's 64 k_main blocks
    // k_main idx = ((mod*8+n)*4 + tile)*8 + cs = mod*256 + n*32 + tile*8 + cs
    if (t < 128) {
        int hc = t & 15, sl = t >> 4;   // 8 slices x 8 entries
        float s = 0.f;
#pragma unroll
        for (int k = 0; k < 8; k++) {
            int rr = sl * 8 + k;        // 0..63 : mod*32 + tile*8 + cs
            int idx = (rr >> 5) * 256 + n * 32 + (rr & 31);
            s += g_bsum[idx][hc];
        }
        red2[sl][hc] = s;
    }

#pragma unroll
    for (int i = t; i < HCc * Ww; i += 256) {
        int hc = i >> 6, x = i & 63;
        int off = hc * HWp + y * Ww + x;
        float r = bR[hc], tv = bT[hc];
#pragma unroll
        for (int cs = 0; cs < CSPLIT; cs++) {
            r  += g_Fp[0][cs][n][0][off];
            tv += g_Fp[1][cs][n][0][off];
        }
        sR[i] = r;
        sT[i] = tv;
    }
    for (int i = t; i < Cc * 4; i += 256) wo[i] = ((const float4*)wO)[i];
    bo[t] = bO[t];
    float scR = sRp[0], scT = sTp[0];
    __syncthreads();

    if (t < HCc) {
        float a = 0.f;
#pragma unroll
        for (int k = 0; k < 8; k++) a += red2[k][t];
        meansm[t] = a * (1.f / 4096.f) + bR[t] + bT[t];
    }
    __syncthreads();
    if (t < HCc) {
        float a = Lb[t];
#pragma unroll
        for (int i = 0; i < HCc; i++) a += meansm[i] * Lw[i * HCc + t];
        wg_sm[t] = 1.f / (1.f + expf(-a));
    }
    __syncthreads();

    int lane = t & 31, w = t >> 5;
#pragma unroll
    for (int hh = 0; hh < 2; hh++) {
        int hc = w + hh * 8;
        float rf0 = sR[hc * Ww + lane], rf1 = sR[hc * Ww + lane + 32];
        float tf0 = sT[hc * Ww + lane], tf1 = sT[hc * Ww + lane + 32];
        float a0 = rf0 * scR, a1 = rf1 * scR;
        float m = fmaxf(a0, a1);
#pragma unroll
        for (int o = 16; o; o >>= 1) m = fmaxf(m, __shfl_xor_sync(0xffffffffu, m, o));
        float e0 = expf(a0 - m), e1 = expf(a1 - m);
        float s = e0 + e1;
#pragma unroll
        for (int o = 16; o; o >>= 1) s += __shfl_xor_sync(0xffffffffu, s, o);
        float inv = 1.f / s;
        float mR0 = e0 * inv, mR1 = e1 * inv;
        float c0 = tf0 * scT, c1 = tf1 * scT;
        float mt = fmaxf(c0, c1);
#pragma unroll
        for (int o = 16; o; o >>= 1) mt = fmaxf(mt, __shfl_xor_sync(0xffffffffu, mt, o));
        float g0 = expf(c0 - mt), g1 = expf(c1 - mt);
        float st = g0 + g1;
#pragma unroll
        for (int o = 16; o; o >>= 1) st += __shfl_xor_sync(0xffffffffu, st, o);
        float invt = 1.f / st;
        float mT0 = g0 * invt, mT1 = g1 * invt;

        float wg = wg_sm[hc];
        fu[hc * Ww + lane]      = mR0 * rf0 + mT0 * tf0 + wg * (rf0 + tf0);
        fu[hc * Ww + lane + 32] = mR1 * rf1 + mT1 * tf1 + wg * (rf1 + tf1);
    }
    __syncthreads();

    int x = t & 63, co0 = t >> 6;
    float fx[HCc];
#pragma unroll
    for (int i = 0; i < HCc; i++) fx[i] = fu[i * Ww + x];
    float* outp = out + (size_t)n * Cc * HWp + y * Ww + x;
    for (int co = co0; co < Cc; co += 4) {
        const float4* wp = &wo[co * 4];
        float a = bo[co];
#pragma unroll
        for (int q = 0; q < 4; q++) {
            float4 ww = wp[q];
            a += ww.x * fx[q*4+0] + ww.y * fx[q*4+1] + ww.z * fx[q*4+2] + ww.w * fx[q*4+3];
        }
        outp[(size_t)co * HWp] = a;
    }
}

// ---------------- launch ----------------
extern "C" void kernel_launch(void* const* d_in, const int* in_sizes, int n_in,
                              void* d_out, int out_size)
{
    const float* R      = (const float*)d_in[0];
    const float* T      = (const float*)d_in[1];
    const float* conv_w = (const float*)d_in[2];
    const float* bn_g   = (const float*)d_in[3];
    const float* bn_b   = (const float*)d_in[4];
    const float* bn_m   = (const float*)d_in[5];
    const float* bn_v   = (const float*)d_in[6];
    const float* f1W1   = (const float*)d_in[7];
    const float* f1b1   = (const float*)d_in[8];
    const float* f1W2R  = (const float*)d_in[9];
    const float* f1b2R  = (const float*)d_in[10];
    const float* f1W2T  = (const float*)d_in[11];
    const float* f1b2T  = (const float*)d_in[12];
    const float* f2W1   = (const float*)d_in[13];
    const float* f2b1   = (const float*)d_in[14];
    const float* f2W2R  = (const float*)d_in[15];
    const float* f2b2R  = (const float*)d_in[16];
    const float* f2W2T  = (const float*)d_in[17];
    const float* f2b2T  = (const float*)d_in[18];
    const float* fv_wR  = (const float*)d_in[19];
    const float* fv_bR  = (const float*)d_in[20];
    const float* fv_wT  = (const float*)d_in[21];
    const float* fv_bT  = (const float*)d_in[22];
    const float* fv_Lw  = (const float*)d_in[23];
    const float* fv_Lb  = (const float*)d_in[24];
    const float* fv_wO  = (const float*)d_in[25];
    const float* fv_bO  = (const float*)d_in[26];
    const float* fv_sR  = (const float*)d_in[27];
    const float* fv_sT  = (const float*)d_in[28];

    float* out  = (float*)d_out;
    float* outR = nullptr;
    float* outO = out;
    if (out_size >= 2 * NCHW) {   // output is (R, out) concatenated
        outR = out;
        outO = out + NCHW;
    }

    k_gap<<<4096, 128>>>(R, T, outR);
    k_vecA<<<144, 256>>>(conv_w, bn_g, bn_b, bn_m, bn_v,
                         f1W1, f1b1, f2W1, f2b1);
    k_vecB<<<32, 256>>>(f1W2R, f1b2R, f1W2T, f1b2T,
                        f2W2R, f2b2R, f2W2T, f2b2T);
    k_main<<<NBLK_MAIN, 256>>>(R, T, fv_wR, fv_wT);
    k_out<<<512, 256>>>(fv_wO, fv_bO, fv_sR, fv_sT, fv_bR, fv_bT,
                        fv_Lw, fv_Lb, outO);
}

// round 13
// speedup vs baseline: 1.1005x; 1.0169x over previous
#include <cuda_runtime.h>
#include <cuda_bf16.h>
#include <cuda_pipeline.h>
#include <cstdint>

// Problem constants
#define Nn   8
#define Cc   256
#define Hh   64
#define Ww   64
#define HWp  4096          // H*W
#define Gr   8             // groups
#define KK2  9             // K*K
#define GKK  72            // G*K*K
#define HIDc 256
#define HCc  16
#define NCHW (8*256*4096)
#define CSPLIT 8
#define CPB   (Cc/CSPLIT)            // 32 channels per block (= one filter group)
#define XT    4                      // x tiles of width 16 (full height)
#define NBLK_MAIN (2*Nn*XT*CSPLIT)   // 512

// ---------------- packed f32x2 helpers (Blackwell) ----------------
__device__ __forceinline__ unsigned long long pack2(float v) {
    unsigned long long r;
    asm("mov.b64 %0, {%1, %1};" : "=l"(r) : "f"(v));
    return r;
}
__device__ __forceinline__ void fma2(unsigned long long& d,
                                     unsigned long long a, unsigned long long b) {
    asm("fma.rn.f32x2 %0, %1, %2, %0;" : "+l"(d) : "l"(a), "l"(b));
}
__device__ __forceinline__ float2 unpack2(unsigned long long v) {
    float2 r;
    asm("mov.b64 {%0, %1}, %2;" : "=f"(r.x), "=f"(r.y) : "l"(v));
    return r;
}

// ---------------- scratch (device globals: no allocation allowed) ----------------
__device__ float  g_gap[2][Nn][Cc];              // per-modality GAP
__device__ float  g_hid[2][Nn][HIDc];            // MLP hidden activations
__device__ float  g_filt[2][Nn][GKK];            // softmaxed dynamic filters
__device__ float2 g_wAB[2][Nn][Cc];              // (wR - wT, wT) gating per channel
__device__ float  g_Fp[2][CSPLIT][Nn][HCc][HWp]; // partial 16-ch features (no bias)
__device__ float  g_bsum[NBLK_MAIN][HCc];        // per-block partial sums for Gf mean

// ---------------- Kernel 1: GAP over H,W (+ copy R to output) ----------------
__global__ void k_gap(const float* __restrict__ R, const float* __restrict__ T,
                      float* __restrict__ outR)
{
    int b   = blockIdx.x;          // 0..4095 : mod*2048 + (n*256+c)
    int mod = b >> 11;
    int nc  = b & 2047;
    const float4* p = (const float4*)((mod ? T : R) + (size_t)nc * HWp);
    float4* q = (mod == 0 && outR) ? (float4*)(outR + (size_t)nc * HWp) : nullptr;
    int t = threadIdx.x;           // 128 threads
    float s = 0.f;
#pragma unroll
    for (int i = 0; i < 8; i++) {
        float4 v = p[t + 128 * i];
        if (q) q[t + 128 * i] = v;
        s += v.x + v.y + v.z + v.w;
    }
#pragma unroll
    for (int o = 16; o; o >>= 1) s += __shfl_down_sync(0xffffffffu, s, o);
    __shared__ float sm[4];
    if ((t & 31) == 0) sm[t >> 5] = s;
    __syncthreads();
    if (t == 0)
        g_gap[mod][nc >> 8][nc & 255] = (sm[0] + sm[1] + sm[2] + sm[3]) * (1.f / 4096.f);
}

// ---------------- Kernel 2a: hidden layer + dynamic filters ----------------
__global__ void k_vecA(const float* __restrict__ conv_w,
                       const float* __restrict__ bn_g, const float* __restrict__ bn_b,
                       const float* __restrict__ bn_m, const float* __restrict__ bn_v,
                       const float* __restrict__ f1W1, const float* __restrict__ f1b1,
                       const float* __restrict__ f2W1, const float* __restrict__ f2b1)
{
    int b = blockIdx.x;
    int j = b % 9;
    int n = (b / 9) & 7;
    int mod = b / 72;
    const float* W1 = mod ? f2W1 : f1W1;
    const float* b1 = mod ? f2b1 : f1b1;

    __shared__ float gp[Cc];
    __shared__ float part[8][32];
    __shared__ float lf_sm[GKK];
    int t = threadIdx.x;          // 256
    gp[t] = g_gap[mod][n][t];
    __syncthreads();

    int lane = t & 31, w = t >> 5;
    if (j < 8) {
        int o = j * 32 + lane;
        const float* Wp = W1 + (size_t)(w * 32) * HIDc + o;
        float s = 0.f;
#pragma unroll
        for (int i = 0; i < 32; i++) s += gp[w * 32 + i] * Wp[(size_t)i * HIDc];
        part[w][lane] = s;
        __syncthreads();
        if (t < 32) {
            float a = b1[j * 32 + t];
#pragma unroll
            for (int ww = 0; ww < 8; ww++) a += part[ww][t];
            g_hid[mod][n][j * 32 + t] = fmaxf(a, 0.f);
        }
    } else {
#pragma unroll
        for (int k = 0; k < KK2; k++) {
            int o = w * KK2 + k;
            const float* cw = conv_w + (size_t)o * Cc;
            float a = 0.f;
#pragma unroll
            for (int q = 0; q < 8; q++) a += gp[lane + 32 * q] * cw[lane + 32 * q];
#pragma unroll
            for (int off = 16; off; off >>= 1) a += __shfl_down_sync(0xffffffffu, a, off);
            if (lane == 0)
                lf_sm[o] = (a - bn_m[o]) * rsqrtf(bn_v[o] + 1e-5f) * bn_g[o] + bn_b[o];
        }
        __syncthreads();
        if (t < Gr) {
            float mx = -1e30f;
#pragma unroll
            for (int k = 0; k < KK2; k++) mx = fmaxf(mx, lf_sm[t * KK2 + k]);
            float e[KK2], sum = 0.f;
#pragma unroll
            for (int k = 0; k < KK2; k++) { e[k] = expf(lf_sm[t * KK2 + k] - mx); sum += e[k]; }
            float inv = 1.f / sum;
#pragma unroll
            for (int k = 0; k < KK2; k++) g_filt[mod][n][t * KK2 + k] = e[k] * inv;
        }
    }
}

// ---------------- Kernel 2b: sigmoid gating layers ----------------
__global__ void k_vecB(const float* __restrict__ f1W2R, const float* __restrict__ f1b2R,
                       const float* __restrict__ f1W2T, const float* __restrict__ f1b2T,
                       const float* __restrict__ f2W2R, const float* __restrict__ f2b2R,
                       const float* __restrict__ f2W2T, const float* __restrict__ f2b2T)
{
    int b = blockIdx.x;
    int half = b & 1;
    int n = (b >> 1) & 7;
    int mod = b >> 4;
    const float* W2R = mod ? f2W2R : f1W2R;
    const float* b2R = mod ? f2b2R : f1b2R;
    const float* W2T = mod ? f2W2T : f1W2T;
    const float* b2T = mod ? f2b2T : f1b2T;

    __shared__ float hid_sm[HIDc];
    __shared__ float psR[8][128], psT[8][128];
    int t = threadIdx.x;          // 256
    hid_sm[t] = g_hid[mod][n][t];
    __syncthreads();

    int lane = t & 31, w = t >> 5;
#pragma unroll
    for (int ch = 0; ch < 4; ch++) {
        int o = half * 128 + ch * 32 + lane;
        float aR = 0.f, aT = 0.f;
#pragma unroll
        for (int i2 = 0; i2 < 32; i2++) {
            float h = hid_sm[w * 32 + i2];
            size_t idx = (size_t)(w * 32 + i2) * Cc + o;
            aR += h * W2R[idx];
            aT += h * W2T[idx];
        }
        psR[w][ch * 32 + lane] = aR;
        psT[w][ch * 32 + lane] = aT;
    }
    __syncthreads();
    if (t < 128) {
        int o = half * 128 + t;
        float aR = b2R[o], aT = b2T[o];
#pragma unroll
        for (int ww = 0; ww < 8; ww++) { aR += psR[ww][t]; aT += psT[ww][t]; }
        float wR = 1.f / (1.f + expf(-aR));
        float wT = 1.f / (1.f + expf(-aT));
        g_wAB[mod][n][o] = make_float2(wR - wT, wT);
    }
}

// ---------------- Kernel 3: involution + gating + 256->16 conv ----------------
// grid = 512: ((mod*8 + n)*4 + tile)*8 + cs. Tile = 16 wide x 64 tall stripe,
// 32 channels (one filter group) per block. 256 threads, 4 vertical px/thread.
// cp.async pipeline at PAIR granularity: 16 iterations x 2 channels, ONE
// barrier per pair. 8 channel buffers, lookahead 2 pairs (4 channels).
#define HSTR  20
#define ROWS  66
#define BUFSZ (ROWS * HSTR)
#define NPAIR (CPB/2)   // 16
#define PLOOK 2         // pairs in flight ahead
__global__ void __launch_bounds__(256, 2) k_main(const float* __restrict__ R,
                                                 const float* __restrict__ T,
                                                 const float* __restrict__ fv_wR,
                                                 const float* __restrict__ fv_wT)
{
    int b    = blockIdx.x;
    int cs   = b & 7;
    int r    = b >> 3;
    int tile = r & 3;
    r >>= 2;
    int n    = r & 7;
    int mod  = r >> 3;
    int tx0  = tile * 16;

    const float* X    = (mod ? T : R) + (size_t)n * Cc * HWp + (size_t)cs * CPB * HWp;
    const float* wmat = mod ? fv_wT : fv_wR;      // [16][256]
    float* Out = &g_Fp[mod][cs][n][0][0];

    __shared__ float  buf[8][BUFSZ];
    __shared__ float  wv[CPB * HCc];       // transposed: wv[c*16+o], c local
    __shared__ float2 ab_sm[CPB];
    __shared__ float  filt_sm[KK2];
    __shared__ float  red[8][HCc];

    int t = threadIdx.x;
    for (int i = t; i < CPB * HCc; i += 256) {
        int o = i >> 5, c = i & 31;
        wv[c * HCc + o] = wmat[o * Cc + cs * CPB + c];
    }
    if (t < CPB) ab_sm[t] = g_wAB[mod][n][cs * CPB + t];
    if (t < KK2) filt_sm[t] = g_filt[mod][n][cs * KK2 + t];   // group == cs

    // ---- cp.async op tables ----
    auto refl = [](int gy) { return gy < 0 ? 1 : (gy > 63 ? 62 : gy); };
    int i16a = t;
    int ra = i16a >> 2, sa = i16a & 3;
    int g16a = refl(ra - 1) * Ww + tx0 + sa * 4;
    int s16a = ra * HSTR + sa * 4;
    bool has16b = t < 8;
    int i16b = t + 256;
    int rb = i16b >> 2, sb = i16b & 3;
    int g16b = refl(rb - 1) * Ww + tx0 + sb * 4;
    int s16b = rb * HSTR + sb * 4;
    bool has4 = t < 132;
    int j4 = has4 ? t : 0;
    int rc = j4 >> 1, side = j4 & 1;
    int gx4 = side ? (tx0 + 16 > 63 ? 62 : tx0 + 16) : (tx0 == 0 ? 1 : tx0 - 1);
    int g4 = refl(rc - 1) * Ww + gx4;
    int s4 = rc * HSTR + 16 + side;

    int tx = t & 15, ty = t >> 4;
    int y0 = ty * 4;               // 4 output rows y0..y0+3
    int offL = (tx == 0)  ? 16 : tx - 1;
    int off0 = tx;
    int offR = (tx == 15) ? 17 : tx + 1;

    unsigned long long accp[4][8];  // f32x2: lanes (hc=2q, hc=2q+1)
#pragma unroll
    for (int j = 0; j < 4; j++)
#pragma unroll
        for (int q = 0; q < 8; q++) accp[j][q] = 0ull;

    __syncthreads();               // wv/ab/filt visible
    float f[KK2];
#pragma unroll
    for (int k = 0; k < KK2; k++) f[k] = filt_sm[k];

    // pipeline prologue: pairs 0..PLOOK-1 (channels 0..2*PLOOK-1)
#pragma unroll
    for (int p = 0; p < PLOOK; p++) {
#pragma unroll
        for (int s = 0; s < 2; s++) {
            int ch = 2 * p + s;
            const float* S = X + (size_t)ch * HWp;
            float* D = buf[ch];
            __pipeline_memcpy_async(&D[s16a], &S[g16a], 16);
            if (has16b) __pipeline_memcpy_async(&D[s16b], &S[g16b], 16);
            if (has4)   __pipeline_memcpy_async(&D[s4],   &S[g4],   4);
        }
        __pipeline_commit();       // one group per pair
    }

    for (int cp = 0; cp < NPAIR; cp++) {
        {   // issue pair cp+PLOOK (channels 2cp+4, 2cp+5 -> buf[(2cp+4..5)&7];
            // readers at channels 2cp..2cp+1 mod 8, max skew 1 iter -> safe)
            int qp = cp + PLOOK;
            if (qp < NPAIR) {
#pragma unroll
                for (int s = 0; s < 2; s++) {
                    int ch = 2 * qp + s;
                    const float* S = X + (size_t)ch * HWp;
                    float* D = buf[ch & 7];
                    __pipeline_memcpy_async(&D[s16a], &S[g16a], 16);
                    if (has16b) __pipeline_memcpy_async(&D[s16b], &S[g16b], 16);
                    if (has4)   __pipeline_memcpy_async(&D[s4],   &S[g4],   4);
                }
            }
            __pipeline_commit();
        }
        __pipeline_wait_prior(PLOOK);
        __syncthreads();           // single barrier per PAIR of channels

#pragma unroll
        for (int s = 0; s < 2; s++) {
            int c = 2 * cp + s;
            const float* Bf = buf[c & 7];
            float2 ab = ab_sm[c];
            float Av[6], Bv[6], Cv[6];
#pragma unroll
            for (int rr = 0; rr < 6; rr++) {
                int o = (y0 + rr) * HSTR;
                Av[rr] = Bf[o + offL];
                Bv[rr] = Bf[o + off0];
                Cv[rr] = Bf[o + offR];
            }
            const unsigned long long* wp = (const unsigned long long*)&wv[c * HCc];
            unsigned long long w2[8];
#pragma unroll
            for (int q = 0; q < 8; q++) w2[q] = wp[q];
#pragma unroll
            for (int j = 0; j < 4; j++) {
                float low = f[0]*Av[j]   + f[1]*Bv[j]   + f[2]*Cv[j]
                          + f[3]*Av[j+1] + f[4]*Bv[j+1] + f[5]*Cv[j+1]
                          + f[6]*Av[j+2] + f[7]*Bv[j+2] + f[8]*Cv[j+2];
                float val = ab.y * Bv[j+1] + ab.x * low;   // wT*X + (wR-wT)*low
                unsigned long long v2 = pack2(val);
#pragma unroll
                for (int q = 0; q < 8; q++) fma2(accp[j][q], w2[q], v2);
            }
        }
    }

    // store partial outputs (no bias)
    int x = tx0 + tx;
#pragma unroll
    for (int q = 0; q < 8; q++)
#pragma unroll
        for (int j = 0; j < 4; j++) {
            float2 u = unpack2(accp[j][q]);
            Out[(2 * q)     * HWp + (y0 + j) * Ww + x] = u.x;
            Out[(2 * q + 1) * HWp + (y0 + j) * Ww + x] = u.y;
        }

    // deterministic per-block reduction for the Gf-mean path
    int lane = t & 31, w = t >> 5;
#pragma unroll
    for (int q = 0; q < 8; q++) {
        float2 s0 = unpack2(accp[0][q]), s1 = unpack2(accp[1][q]);
        float2 s2 = unpack2(accp[2][q]), s3 = unpack2(accp[3][q]);
        float vx = s0.x + s1.x + s2.x + s3.x;
        float vy = s0.y + s1.y + s2.y + s3.y;
#pragma unroll
        for (int o = 16; o; o >>= 1) {
            vx += __shfl_down_sync(0xffffffffu, vx, o);
            vy += __shfl_down_sync(0xffffffffu, vy, o);
        }
        if (lane == 0) { red[w][2 * q] = vx; red[w][2 * q + 1] = vy; }
    }
    __syncthreads();
    if (t < HCc) {
        float s = 0.f;
#pragma unroll
        for (int ww = 0; ww < 8; ww++) s += red[ww][t];
        g_bsum[blockIdx.x][t] = s;
    }
}

// ---------------- Kernel 4: fovea softmax + inline wG gate + 16->256 conv ----------
__global__ void __launch_bounds__(256) k_out(const float* __restrict__ wO,
                                             const float* __restrict__ bO,
                                             const float* __restrict__ sRp,
                                             const float* __restrict__ sTp,
                                             const float* __restrict__ bR,
                                             const float* __restrict__ bT,
                                             const float* __restrict__ Lw,
                                             const float* __restrict__ Lb,
                                             float* __restrict__ out)
{
    int b = blockIdx.x;            // 512: n*64 + y
    int n = b >> 6, y = b & 63;
    __shared__ float  sR[HCc * Ww], sT[HCc * Ww], fu[HCc * Ww];
    __shared__ float4 wo[Cc * 4];  // wO rows as float4: wo[co*4+q]
    __shared__ float  bo[Cc];
    __shared__ float  red2[8][HCc], meansm[HCc], wg_sm[HCc];
    int t = threadIdx.x;

    // inline wG: sum g_bsum over this n's 64 k_main blocks
    // k_main idx = ((mod*8+n)*4 + tile)*8 + cs = mod*256 + n*32 + tile*8 + cs
    if (t < 128) {
        int hc = t & 15, sl = t >> 4;   // 8 slices x 8 entries
        float s = 0.f;
#pragma unroll
        for (int k = 0; k < 8; k++) {
            int rr = sl * 8 + k;        // 0..63 : mod*32 + tile*8 + cs
            int idx = (rr >> 5) * 256 + n * 32 + (rr & 31);
            s += g_bsum[idx][hc];
        }
        red2[sl][hc] = s;
    }

#pragma unroll
    for (int i = t; i < HCc * Ww; i += 256) {
        int hc = i >> 6, x = i & 63;
        int off = hc * HWp + y * Ww + x;
        float r = bR[hc], tv = bT[hc];
#pragma unroll
        for (int cs = 0; cs < CSPLIT; cs++) {
            r  += g_Fp[0][cs][n][0][off];
            tv += g_Fp[1][cs][n][0][off];
        }
        sR[i] = r;
        sT[i] = tv;
    }
    for (int i = t; i < Cc * 4; i += 256) wo[i] = ((const float4*)wO)[i];
    bo[t] = bO[t];
    float scR = sRp[0], scT = sTp[0];
    __syncthreads();

    if (t < HCc) {
        float a = 0.f;
#pragma unroll
        for (int k = 0; k < 8; k++) a += red2[k][t];
        meansm[t] = a * (1.f / 4096.f) + bR[t] + bT[t];
    }
    __syncthreads();
    if (t < HCc) {
        float a = Lb[t];
#pragma unroll
        for (int i = 0; i < HCc; i++) a += meansm[i] * Lw[i * HCc + t];
        wg_sm[t] = 1.f / (1.f + expf(-a));
    }
    __syncthreads();

    int lane = t & 31, w = t >> 5;
#pragma unroll
    for (int hh = 0; hh < 2; hh++) {
        int hc = w + hh * 8;
        float rf0 = sR[hc * Ww + lane], rf1 = sR[hc * Ww + lane + 32];
        float tf0 = sT[hc * Ww + lane], tf1 = sT[hc * Ww + lane + 32];
        float a0 = rf0 * scR, a1 = rf1 * scR;
        float m = fmaxf(a0, a1);
#pragma unroll
        for (int o = 16; o; o >>= 1) m = fmaxf(m, __shfl_xor_sync(0xffffffffu, m, o));
        float e0 = expf(a0 - m), e1 = expf(a1 - m);
        float s = e0 + e1;
#pragma unroll
        for (int o = 16; o; o >>= 1) s += __shfl_xor_sync(0xffffffffu, s, o);
        float inv = 1.f / s;
        float mR0 = e0 * inv, mR1 = e1 * inv;
        float c0 = tf0 * scT, c1 = tf1 * scT;
        float mt = fmaxf(c0, c1);
#pragma unroll
        for (int o = 16; o; o >>= 1) mt = fmaxf(mt, __shfl_xor_sync(0xffffffffu, mt, o));
        float g0 = expf(c0 - mt), g1 = expf(c1 - mt);
        float st = g0 + g1;
#pragma unroll
        for (int o = 16; o; o >>= 1) st += __shfl_xor_sync(0xffffffffu, st, o);
        float invt = 1.f / st;
        float mT0 = g0 * invt, mT1 = g1 * invt;

        float wg = wg_sm[hc];
        fu[hc * Ww + lane]      = mR0 * rf0 + mT0 * tf0 + wg * (rf0 + tf0);
        fu[hc * Ww + lane + 32] = mR1 * rf1 + mT1 * tf1 + wg * (rf1 + tf1);
    }
    __syncthreads();

    int x = t & 63, co0 = t >> 6;
    float fx[HCc];
#pragma unroll
    for (int i = 0; i < HCc; i++) fx[i] = fu[i * Ww + x];
    float* outp = out + (size_t)n * Cc * HWp + y * Ww + x;
    for (int co = co0; co < Cc; co += 4) {
        const float4* wp = &wo[co * 4];
        float a = bo[co];
#pragma unroll
        for (int q = 0; q < 4; q++) {
            float4 ww = wp[q];
            a += ww.x * fx[q*4+0] + ww.y * fx[q*4+1] + ww.z * fx[q*4+2] + ww.w * fx[q*4+3];
        }
        outp[(size_t)co * HWp] = a;
    }
}

// ---------------- launch ----------------
extern "C" void kernel_launch(void* const* d_in, const int* in_sizes, int n_in,
                              void* d_out, int out_size)
{
    const float* R      = (const float*)d_in[0];
    const float* T      = (const float*)d_in[1];
    const float* conv_w = (const float*)d_in[2];
    const float* bn_g   = (const float*)d_in[3];
    const float* bn_b   = (const float*)d_in[4];
    const float* bn_m   = (const float*)d_in[5];
    const float* bn_v   = (const float*)d_in[6];
    const float* f1W1   = (const float*)d_in[7];
    const float* f1b1   = (const float*)d_in[8];
    const float* f1W2R  = (const float*)d_in[9];
    const float* f1b2R  = (const float*)d_in[10];
    const float* f1W2T  = (const float*)d_in[11];
    const float* f1b2T  = (const float*)d_in[12];
    const float* f2W1   = (const float*)d_in[13];
    const float* f2b1   = (const float*)d_in[14];
    const float* f2W2R  = (const float*)d_in[15];
    const float* f2b2R  = (const float*)d_in[16];
    const float* f2W2T  = (const float*)d_in[17];
    const float* f2b2T  = (const float*)d_in[18];
    const float* fv_wR  = (const float*)d_in[19];
    const float* fv_bR  = (const float*)d_in[20];
    const float* fv_wT  = (const float*)d_in[21];
    const float* fv_bT  = (const float*)d_in[22];
    const float* fv_Lw  = (const float*)d_in[23];
    const float* fv_Lb  = (const float*)d_in[24];
    const float* fv_wO  = (const float*)d_in[25];
    const float* fv_bO  = (const float*)d_in[26];
    const float* fv_sR  = (const float*)d_in[27];
    const float* fv_sT  = (const float*)d_in[28];

    float* out  = (float*)d_out;
    float* outR = nullptr;
    float* outO = out;
    if (out_size >= 2 * NCHW) {   // output is (R, out) concatenated
        outR = out;
        outO = out + NCHW;
    }

    k_gap<<<4096, 128>>>(R, T, outR);
    k_vecA<<<144, 256>>>(conv_w, bn_g, bn_b, bn_m, bn_v,
                         f1W1, f1b1, f2W1, f2b1);
    k_vecB<<<32, 256>>>(f1W2R, f1b2R, f1W2T, f1b2T,
                        f2W2R, f2b2R, f2W2T, f2b2T);
    k_main<<<NBLK_MAIN, 256>>>(R, T, fv_wR, fv_wT);
    k_out<<<512, 256>>>(fv_wO, fv_bO, fv_sR, fv_sT, fv_bR, fv_bT,
                        fv_Lw, fv_Lb, outO);
}

// round 14
// speedup vs baseline: 1.1162x; 1.0143x over previous
#include <cuda_runtime.h>
#include <cuda_bf16.h>
#include <cuda_pipeline.h>
#include <cstdint>

// Problem constants
#define Nn   8
#define Cc   256
#define Hh   64
#define Ww   64
#define HWp  4096          // H*W
#define Gr   8             // groups
#define KK2  9             // K*K
#define GKK  72            // G*K*K
#define HIDc 256
#define HCc  16
#define NCHW (8*256*4096)
#define CSPLIT 8
#define CPB   (Cc/CSPLIT)            // 32 channels per block (= one filter group)
#define XT    4                      // x tiles of width 16 (full height)
#define NBLK_MAIN (2*Nn*XT*CSPLIT)   // 512

// ---------------- packed f32x2 helpers (Blackwell) ----------------
__device__ __forceinline__ unsigned long long pack2(float v) {
    unsigned long long r;
    asm("mov.b64 %0, {%1, %1};" : "=l"(r) : "f"(v));
    return r;
}
__device__ __forceinline__ void fma2(unsigned long long& d,
                                     unsigned long long a, unsigned long long b) {
    asm("fma.rn.f32x2 %0, %1, %2, %0;" : "+l"(d) : "l"(a), "l"(b));
}
__device__ __forceinline__ float2 unpack2(unsigned long long v) {
    float2 r;
    asm("mov.b64 {%0, %1}, %2;" : "=f"(r.x), "=f"(r.y) : "l"(v));
    return r;
}

// ---------------- scratch (device globals: no allocation allowed) ----------------
__device__ float  g_gap[2][Nn][Cc];              // per-modality GAP
__device__ float  g_hid[2][Nn][HIDc];            // MLP hidden activations
__device__ float  g_filt[2][Nn][GKK];            // softmaxed dynamic filters
__device__ float2 g_wAB[2][Nn][Cc];              // (wR - wT, wT) gating per channel
__device__ float  g_Fp[2][CSPLIT][Nn][HCc][HWp]; // partial 16-ch features (no bias)
__device__ float  g_bsum[NBLK_MAIN][HCc];        // per-block partial sums for Gf mean

// ---------------- Kernel 1: GAP over H,W (+ copy R to output) ----------------
__global__ void k_gap(const float* __restrict__ R, const float* __restrict__ T,
                      float* __restrict__ outR)
{
    int b   = blockIdx.x;          // 0..4095 : mod*2048 + (n*256+c)
    int mod = b >> 11;
    int nc  = b & 2047;
    const float4* p = (const float4*)((mod ? T : R) + (size_t)nc * HWp);
    float4* q = (mod == 0 && outR) ? (float4*)(outR + (size_t)nc * HWp) : nullptr;
    int t = threadIdx.x;           // 128 threads
    float s = 0.f;
#pragma unroll
    for (int i = 0; i < 8; i++) {
        float4 v = p[t + 128 * i];
        if (q) q[t + 128 * i] = v;
        s += v.x + v.y + v.z + v.w;
    }
#pragma unroll
    for (int o = 16; o; o >>= 1) s += __shfl_down_sync(0xffffffffu, s, o);
    __shared__ float sm[4];
    if ((t & 31) == 0) sm[t >> 5] = s;
    __syncthreads();
    if (t == 0)
        g_gap[mod][nc >> 8][nc & 255] = (sm[0] + sm[1] + sm[2] + sm[3]) * (1.f / 4096.f);
}

// ---------------- Kernel 2a: hidden layer + dynamic filters ----------------
__global__ void k_vecA(const float* __restrict__ conv_w,
                       const float* __restrict__ bn_g, const float* __restrict__ bn_b,
                       const float* __restrict__ bn_m, const float* __restrict__ bn_v,
                       const float* __restrict__ f1W1, const float* __restrict__ f1b1,
                       const float* __restrict__ f2W1, const float* __restrict__ f2b1)
{
    int b = blockIdx.x;
    int j = b % 9;
    int n = (b / 9) & 7;
    int mod = b / 72;
    const float* W1 = mod ? f2W1 : f1W1;
    const float* b1 = mod ? f2b1 : f1b1;

    __shared__ float gp[Cc];
    __shared__ float part[8][32];
    __shared__ float lf_sm[GKK];
    int t = threadIdx.x;          // 256
    gp[t] = g_gap[mod][n][t];
    __syncthreads();

    int lane = t & 31, w = t >> 5;
    if (j < 8) {
        int o = j * 32 + lane;
        const float* Wp = W1 + (size_t)(w * 32) * HIDc + o;
        float s = 0.f;
#pragma unroll
        for (int i = 0; i < 32; i++) s += gp[w * 32 + i] * Wp[(size_t)i * HIDc];
        part[w][lane] = s;
        __syncthreads();
        if (t < 32) {
            float a = b1[j * 32 + t];
#pragma unroll
            for (int ww = 0; ww < 8; ww++) a += part[ww][t];
            g_hid[mod][n][j * 32 + t] = fmaxf(a, 0.f);
        }
    } else {
#pragma unroll
        for (int k = 0; k < KK2; k++) {
            int o = w * KK2 + k;
            const float* cw = conv_w + (size_t)o * Cc;
            float a = 0.f;
#pragma unroll
            for (int q = 0; q < 8; q++) a += gp[lane + 32 * q] * cw[lane + 32 * q];
#pragma unroll
            for (int off = 16; off; off >>= 1) a += __shfl_down_sync(0xffffffffu, a, off);
            if (lane == 0)
                lf_sm[o] = (a - bn_m[o]) * rsqrtf(bn_v[o] + 1e-5f) * bn_g[o] + bn_b[o];
        }
        __syncthreads();
        if (t < Gr) {
            float mx = -1e30f;
#pragma unroll
            for (int k = 0; k < KK2; k++) mx = fmaxf(mx, lf_sm[t * KK2 + k]);
            float e[KK2], sum = 0.f;
#pragma unroll
            for (int k = 0; k < KK2; k++) { e[k] = expf(lf_sm[t * KK2 + k] - mx); sum += e[k]; }
            float inv = 1.f / sum;
#pragma unroll
            for (int k = 0; k < KK2; k++) g_filt[mod][n][t * KK2 + k] = e[k] * inv;
        }
    }
}

// ---------------- Kernel 2b: sigmoid gating layers ----------------
__global__ void k_vecB(const float* __restrict__ f1W2R, const float* __restrict__ f1b2R,
                       const float* __restrict__ f1W2T, const float* __restrict__ f1b2T,
                       const float* __restrict__ f2W2R, const float* __restrict__ f2b2R,
                       const float* __restrict__ f2W2T, const float* __restrict__ f2b2T)
{
    int b = blockIdx.x;
    int half = b & 1;
    int n = (b >> 1) & 7;
    int mod = b >> 4;
    const float* W2R = mod ? f2W2R : f1W2R;
    const float* b2R = mod ? f2b2R : f1b2R;
    const float* W2T = mod ? f2W2T : f1W2T;
    const float* b2T = mod ? f2b2T : f1b2T;

    __shared__ float hid_sm[HIDc];
    __shared__ float psR[8][128], psT[8][128];
    int t = threadIdx.x;          // 256
    hid_sm[t] = g_hid[mod][n][t];
    __syncthreads();

    int lane = t & 31, w = t >> 5;
#pragma unroll
    for (int ch = 0; ch < 4; ch++) {
        int o = half * 128 + ch * 32 + lane;
        float aR = 0.f, aT = 0.f;
#pragma unroll
        for (int i2 = 0; i2 < 32; i2++) {
            float h = hid_sm[w * 32 + i2];
            size_t idx = (size_t)(w * 32 + i2) * Cc + o;
            aR += h * W2R[idx];
            aT += h * W2T[idx];
        }
        psR[w][ch * 32 + lane] = aR;
        psT[w][ch * 32 + lane] = aT;
    }
    __syncthreads();
    if (t < 128) {
        int o = half * 128 + t;
        float aR = b2R[o], aT = b2T[o];
#pragma unroll
        for (int ww = 0; ww < 8; ww++) { aR += psR[ww][t]; aT += psT[ww][t]; }
        float wR = 1.f / (1.f + expf(-aR));
        float wT = 1.f / (1.f + expf(-aT));
        g_wAB[mod][n][o] = make_float2(wR - wT, wT);
    }
}

// ---------------- Kernel 3: involution + gating + 256->16 conv ----------------
// grid = 512: ((mod*8 + n)*4 + tile)*8 + cs. Tile = 16 wide x 64 tall stripe,
// 32 channels (one filter group) per block. 256 threads, 4 vertical px/thread.
// cp.async pipeline at QUAD granularity: 8 iterations x 4 channels, ONE
// barrier per quad. 8 channel buffers (reader/writer in disjoint halves).
#define HSTR  20
#define ROWS  66
#define BUFSZ (ROWS * HSTR)
#define NQUAD (CPB/4)   // 8
__global__ void __launch_bounds__(256, 2) k_main(const float* __restrict__ R,
                                                 const float* __restrict__ T,
                                                 const float* __restrict__ fv_wR,
                                                 const float* __restrict__ fv_wT)
{
    int b    = blockIdx.x;
    int cs   = b & 7;
    int r    = b >> 3;
    int tile = r & 3;
    r >>= 2;
    int n    = r & 7;
    int mod  = r >> 3;
    int tx0  = tile * 16;

    const float* X    = (mod ? T : R) + (size_t)n * Cc * HWp + (size_t)cs * CPB * HWp;
    const float* wmat = mod ? fv_wT : fv_wR;      // [16][256]
    float* Out = &g_Fp[mod][cs][n][0][0];

    __shared__ float  buf[8][BUFSZ];
    __shared__ float  wv[CPB * HCc];       // transposed: wv[c*16+o], c local
    __shared__ float2 ab_sm[CPB];
    __shared__ float  filt_sm[KK2];
    __shared__ float  red[8][HCc];

    int t = threadIdx.x;
    for (int i = t; i < CPB * HCc; i += 256) {
        int o = i >> 5, c = i & 31;
        wv[c * HCc + o] = wmat[o * Cc + cs * CPB + c];
    }
    if (t < CPB) ab_sm[t] = g_wAB[mod][n][cs * CPB + t];
    if (t < KK2) filt_sm[t] = g_filt[mod][n][cs * KK2 + t];   // group == cs

    // ---- cp.async op tables ----
    auto refl = [](int gy) { return gy < 0 ? 1 : (gy > 63 ? 62 : gy); };
    int i16a = t;
    int ra = i16a >> 2, sa = i16a & 3;
    int g16a = refl(ra - 1) * Ww + tx0 + sa * 4;
    int s16a = ra * HSTR + sa * 4;
    bool has16b = t < 8;
    int i16b = t + 256;
    int rb = i16b >> 2, sb = i16b & 3;
    int g16b = refl(rb - 1) * Ww + tx0 + sb * 4;
    int s16b = rb * HSTR + sb * 4;
    bool has4 = t < 132;
    int j4 = has4 ? t : 0;
    int rc = j4 >> 1, side = j4 & 1;
    int gx4 = side ? (tx0 + 16 > 63 ? 62 : tx0 + 16) : (tx0 == 0 ? 1 : tx0 - 1);
    int g4 = refl(rc - 1) * Ww + gx4;
    int s4 = rc * HSTR + 16 + side;

    int tx = t & 15, ty = t >> 4;
    int y0 = ty * 4;               // 4 output rows y0..y0+3
    int offL = (tx == 0)  ? 16 : tx - 1;
    int off0 = tx;
    int offR = (tx == 15) ? 17 : tx + 1;

    unsigned long long accp[4][8];  // f32x2: lanes (hc=2q, hc=2q+1)
#pragma unroll
    for (int j = 0; j < 4; j++)
#pragma unroll
        for (int q = 0; q < 8; q++) accp[j][q] = 0ull;

    __syncthreads();               // wv/ab/filt visible
    float f[KK2];
#pragma unroll
    for (int k = 0; k < KK2; k++) f[k] = filt_sm[k];

    // pipeline prologue: quad 0 (channels 0..3), one commit group
#pragma unroll
    for (int s = 0; s < 4; s++) {
        const float* S = X + (size_t)s * HWp;
        float* D = buf[s];
        __pipeline_memcpy_async(&D[s16a], &S[g16a], 16);
        if (has16b) __pipeline_memcpy_async(&D[s16b], &S[g16b], 16);
        if (has4)   __pipeline_memcpy_async(&D[s4],   &S[g4],   4);
    }
    __pipeline_commit();

    for (int cq = 0; cq < NQUAD; cq++) {
        {   // issue quad cq+1 (channels 4cq+4..4cq+7 -> other half of ring)
            int qq = cq + 1;
            if (qq < NQUAD) {
#pragma unroll
                for (int s = 0; s < 4; s++) {
                    int ch = 4 * qq + s;
                    const float* S = X + (size_t)ch * HWp;
                    float* D = buf[ch & 7];
                    __pipeline_memcpy_async(&D[s16a], &S[g16a], 16);
                    if (has16b) __pipeline_memcpy_async(&D[s16b], &S[g16b], 16);
                    if (has4)   __pipeline_memcpy_async(&D[s4],   &S[g4],   4);
                }
            }
            __pipeline_commit();
        }
        __pipeline_wait_prior(1);  // quad cq complete (only quad cq+1 outstanding)
        __syncthreads();           // single barrier per QUAD of channels

#pragma unroll
        for (int s = 0; s < 4; s++) {
            int c = 4 * cq + s;
            const float* Bf = buf[c & 7];
            float2 ab = ab_sm[c];
            float Av[6], Bv[6], Cv[6];
#pragma unroll
            for (int rr = 0; rr < 6; rr++) {
                int o = (y0 + rr) * HSTR;
                Av[rr] = Bf[o + offL];
                Bv[rr] = Bf[o + off0];
                Cv[rr] = Bf[o + offR];
            }
            const unsigned long long* wp = (const unsigned long long*)&wv[c * HCc];
            unsigned long long w2[8];
#pragma unroll
            for (int q = 0; q < 8; q++) w2[q] = wp[q];
#pragma unroll
            for (int j = 0; j < 4; j++) {
                float low = f[0]*Av[j]   + f[1]*Bv[j]   + f[2]*Cv[j]
                          + f[3]*Av[j+1] + f[4]*Bv[j+1] + f[5]*Cv[j+1]
                          + f[6]*Av[j+2] + f[7]*Bv[j+2] + f[8]*Cv[j+2];
                float val = ab.y * Bv[j+1] + ab.x * low;   // wT*X + (wR-wT)*low
                unsigned long long v2 = pack2(val);
#pragma unroll
                for (int q = 0; q < 8; q++) fma2(accp[j][q], w2[q], v2);
            }
        }
    }

    // store partial outputs (no bias)
    int x = tx0 + tx;
#pragma unroll
    for (int q = 0; q < 8; q++)
#pragma unroll
        for (int j = 0; j < 4; j++) {
            float2 u = unpack2(accp[j][q]);
            Out[(2 * q)     * HWp + (y0 + j) * Ww + x] = u.x;
            Out[(2 * q + 1) * HWp + (y0 + j) * Ww + x] = u.y;
        }

    // deterministic per-block reduction for the Gf-mean path
    int lane = t & 31, w = t >> 5;
#pragma unroll
    for (int q = 0; q < 8; q++) {
        float2 s0 = unpack2(accp[0][q]), s1 = unpack2(accp[1][q]);
        float2 s2 = unpack2(accp[2][q]), s3 = unpack2(accp[3][q]);
        float vx = s0.x + s1.x + s2.x + s3.x;
        float vy = s0.y + s1.y + s2.y + s3.y;
#pragma unroll
        for (int o = 16; o; o >>= 1) {
            vx += __shfl_down_sync(0xffffffffu, vx, o);
            vy += __shfl_down_sync(0xffffffffu, vy, o);
        }
        if (lane == 0) { red[w][2 * q] = vx; red[w][2 * q + 1] = vy; }
    }
    __syncthreads();
    if (t < HCc) {
        float s = 0.f;
#pragma unroll
        for (int ww = 0; ww < 8; ww++) s += red[ww][t];
        g_bsum[blockIdx.x][t] = s;
    }
}

// ---------------- Kernel 4: fovea softmax + inline wG gate + 16->256 conv ----------
__global__ void __launch_bounds__(256) k_out(const float* __restrict__ wO,
                                             const float* __restrict__ bO,
                                             const float* __restrict__ sRp,
                                             const float* __restrict__ sTp,
                                             const float* __restrict__ bR,
                                             const float* __restrict__ bT,
                                             const float* __restrict__ Lw,
                                             const float* __restrict__ Lb,
                                             float* __restrict__ out)
{
    int b = blockIdx.x;            // 512: n*64 + y
    int n = b >> 6, y = b & 63;
    __shared__ float  sR[HCc * Ww], sT[HCc * Ww], fu[HCc * Ww];
    __shared__ float4 wo[Cc * 4];  // wO rows as float4: wo[co*4+q]
    __shared__ float  bo[Cc];
    __shared__ float  red2[8][HCc], meansm[HCc], wg_sm[HCc];
    int t = threadIdx.x;

    // inline wG: sum g_bsum over this n's 64 k_main blocks
    // k_main idx = ((mod*8+n)*4 + tile)*8 + cs = mod*256 + n*32 + tile*8 + cs
    if (t < 128) {
        int hc = t & 15, sl = t >> 4;   // 8 slices x 8 entries
        float s = 0.f;
#pragma unroll
        for (int k = 0; k < 8; k++) {
            int rr = sl * 8 + k;        // 0..63 : mod*32 + tile*8 + cs
            int idx = (rr >> 5) * 256 + n * 32 + (rr & 31);
            s += g_bsum[idx][hc];
        }
        red2[sl][hc] = s;
    }

#pragma unroll
    for (int i = t; i < HCc * Ww; i += 256) {
        int hc = i >> 6, x = i & 63;
        int off = hc * HWp + y * Ww + x;
        float r = bR[hc], tv = bT[hc];
#pragma unroll
        for (int cs = 0; cs < CSPLIT; cs++) {
            r  += g_Fp[0][cs][n][0][off];
            tv += g_Fp[1][cs][n][0][off];
        }
        sR[i] = r;
        sT[i] = tv;
    }
    for (int i = t; i < Cc * 4; i += 256) wo[i] = ((const float4*)wO)[i];
    bo[t] = bO[t];
    float scR = sRp[0], scT = sTp[0];
    __syncthreads();

    if (t < HCc) {
        float a = 0.f;
#pragma unroll
        for (int k = 0; k < 8; k++) a += red2[k][t];
        meansm[t] = a * (1.f / 4096.f) + bR[t] + bT[t];
    }
    __syncthreads();
    if (t < HCc) {
        float a = Lb[t];
#pragma unroll
        for (int i = 0; i < HCc; i++) a += meansm[i] * Lw[i * HCc + t];
        wg_sm[t] = 1.f / (1.f + expf(-a));
    }
    __syncthreads();

    int lane = t & 31, w = t >> 5;
#pragma unroll
    for (int hh = 0; hh < 2; hh++) {
        int hc = w + hh * 8;
        float rf0 = sR[hc * Ww + lane], rf1 = sR[hc * Ww + lane + 32];
        float tf0 = sT[hc * Ww + lane], tf1 = sT[hc * Ww + lane + 32];
        float a0 = rf0 * scR, a1 = rf1 * scR;
        float m = fmaxf(a0, a1);
#pragma unroll
        for (int o = 16; o; o >>= 1) m = fmaxf(m, __shfl_xor_sync(0xffffffffu, m, o));
        float e0 = expf(a0 - m), e1 = expf(a1 - m);
        float s = e0 + e1;
#pragma unroll
        for (int o = 16; o; o >>= 1) s += __shfl_xor_sync(0xffffffffu, s, o);
        float inv = 1.f / s;
        float mR0 = e0 * inv, mR1 = e1 * inv;
        float c0 = tf0 * scT, c1 = tf1 * scT;
        float mt = fmaxf(c0, c1);
#pragma unroll
        for (int o = 16; o; o >>= 1) mt = fmaxf(mt, __shfl_xor_sync(0xffffffffu, mt, o));
        float g0 = expf(c0 - mt), g1 = expf(c1 - mt);
        float st = g0 + g1;
#pragma unroll
        for (int o = 16; o; o >>= 1) st += __shfl_xor_sync(0xffffffffu, st, o);
        float invt = 1.f / st;
        float mT0 = g0 * invt, mT1 = g1 * invt;

        float wg = wg_sm[hc];
        fu[hc * Ww + lane]      = mR0 * rf0 + mT0 * tf0 + wg * (rf0 + tf0);
        fu[hc * Ww + lane + 32] = mR1 * rf1 + mT1 * tf1 + wg * (rf1 + tf1);
    }
    __syncthreads();

    int x = t & 63, co0 = t >> 6;
    float fx[HCc];
#pragma unroll
    for (int i = 0; i < HCc; i++) fx[i] = fu[i * Ww + x];
    float* outp = out + (size_t)n * Cc * HWp + y * Ww + x;
    for (int co = co0; co < Cc; co += 4) {
        const float4* wp = &wo[co * 4];
        float a = bo[co];
#pragma unroll
        for (int q = 0; q < 4; q++) {
            float4 ww = wp[q];
            a += ww.x * fx[q*4+0] + ww.y * fx[q*4+1] + ww.z * fx[q*4+2] + ww.w * fx[q*4+3];
        }
        outp[(size_t)co * HWp] = a;
    }
}

// ---------------- launch ----------------
extern "C" void kernel_launch(void* const* d_in, const int* in_sizes, int n_in,
                              void* d_out, int out_size)
{
    const float* R      = (const float*)d_in[0];
    const float* T      = (const float*)d_in[1];
    const float* conv_w = (const float*)d_in[2];
    const float* bn_g   = (const float*)d_in[3];
    const float* bn_b   = (const float*)d_in[4];
    const float* bn_m   = (const float*)d_in[5];
    const float* bn_v   = (const float*)d_in[6];
    const float* f1W1   = (const float*)d_in[7];
    const float* f1b1   = (const float*)d_in[8];
    const float* f1W2R  = (const float*)d_in[9];
    const float* f1b2R  = (const float*)d_in[10];
    const float* f1W2T  = (const float*)d_in[11];
    const float* f1b2T  = (const float*)d_in[12];
    const float* f2W1   = (const float*)d_in[13];
    const float* f2b1   = (const float*)d_in[14];
    const float* f2W2R  = (const float*)d_in[15];
    const float* f2b2R  = (const float*)d_in[16];
    const float* f2W2T  = (const float*)d_in[17];
    const float* f2b2T  = (const float*)d_in[18];
    const float* fv_wR  = (const float*)d_in[19];
    const float* fv_bR  = (const float*)d_in[20];
    const float* fv_wT  = (const float*)d_in[21];
    const float* fv_bT  = (const float*)d_in[22];
    const float* fv_Lw  = (const float*)d_in[23];
    const float* fv_Lb  = (const float*)d_in[24];
    const float* fv_wO  = (const float*)d_in[25];
    const float* fv_bO  = (const float*)d_in[26];
    const float* fv_sR  = (const float*)d_in[27];
    const float* fv_sT  = (const float*)d_in[28];

    float* out  = (float*)d_out;
    float* outR = nullptr;
    float* outO = out;
    if (out_size >= 2 * NCHW) {   // output is (R, out) concatenated
        outR = out;
        outO = out + NCHW;
    }

    k_gap<<<4096, 128>>>(R, T, outR);
    k_vecA<<<144, 256>>>(conv_w, bn_g, bn_b, bn_m, bn_v,
                         f1W1, f1b1, f2W1, f2b1);
    k_vecB<<<32, 256>>>(f1W2R, f1b2R, f1W2T, f1b2T,
                        f2W2R, f2b2R, f2W2T, f2b2T);
    k_main<<<NBLK_MAIN, 256>>>(R, T, fv_wR, fv_wT);
    k_out<<<512, 256>>>(fv_wO, fv_bO, fv_sR, fv_sT, fv_bR, fv_bT,
                        fv_Lw, fv_Lb, outO);
}